// round 1
// baseline (speedup 1.0000x reference)
#include <cuda_runtime.h>
#include <cuda_bf16.h>
#include <cstdint>

#define NN 100000
#define NE 3200000

// ---------------- static device scratch (no allocations allowed) ----------------
__device__ int   g_deg[NN];
__device__ int   g_off[NN + 1];
__device__ int   g_cursor[NN];
__device__ int2  g_edge[NE];          // (src, bitcast(attn)) sorted by dst
__device__ float g_hn[(size_t)NN * 128]; // aggregation result, row stride = IN of layer

// ---------------- CSR build ----------------
__global__ void k_zero_deg() {
    int i = blockIdx.x * blockDim.x + threadIdx.x;
    if (i < NN) g_deg[i] = 0;
}

__global__ void k_hist(const int* __restrict__ dst) {
    int e = blockIdx.x * blockDim.x + threadIdx.x;
    if (e < NE) atomicAdd(&g_deg[dst[e]], 1);
}

// single-block exclusive scan over g_deg -> g_off (+ init g_cursor)
__global__ void k_scan() {
    __shared__ int sm[1024];
    __shared__ int s_carry;
    int tid = threadIdx.x;
    if (tid == 0) s_carry = 0;
    __syncthreads();
    for (int base = 0; base < NN; base += 1024) {
        int i = base + tid;
        int v = (i < NN) ? g_deg[i] : 0;
        sm[tid] = v;
        __syncthreads();
        #pragma unroll
        for (int off = 1; off < 1024; off <<= 1) {
            int t = (tid >= off) ? sm[tid - off] : 0;
            __syncthreads();
            sm[tid] += t;
            __syncthreads();
        }
        int carry = s_carry;
        if (i < NN) {
            int ex = carry + sm[tid] - v;
            g_off[i] = ex;
            g_cursor[i] = ex;
        }
        __syncthreads();
        if (tid == 1023) s_carry = carry + sm[1023];
        __syncthreads();
    }
    if (tid == 0) g_off[NN] = s_carry;
}

__global__ void k_scatter(const int* __restrict__ src, const int* __restrict__ dst,
                          const float* __restrict__ attn) {
    int e = blockIdx.x * blockDim.x + threadIdx.x;
    if (e < NE) {
        int d = dst[e];
        int p = atomicAdd(&g_cursor[d], 1);
        g_edge[p] = make_int2(src[e], __float_as_int(attn[e]));
    }
}

// ---------------- copy x into output cols [0,128) ----------------
__global__ void k_copy_x(const float* __restrict__ x, float* __restrict__ out) {
    int t = blockIdx.x * blockDim.x + threadIdx.x;
    if (t < NN * 32) {
        int v = t >> 5, c = t & 31;
        const float4* s = (const float4*)(x + (size_t)v * 128);
        float4* d = (float4*)(out + (size_t)v * 352);
        d[c] = s[c];
    }
}

// ---------------- aggregation: warp per dst node, CSR gather ----------------
// VEC=4 -> D=128 (lane handles float4), VEC=2 -> D=64 (lane handles float2)
template <int VEC>
__global__ void k_agg(const float* __restrict__ xin, int xstride) {
    int gw = (blockIdx.x * blockDim.x + threadIdx.x) >> 5;
    if (gw >= NN) return;
    int lane = threadIdx.x & 31;
    int beg = g_off[gw], end = g_off[gw + 1];

    if (VEC == 4) {
        float4 acc = make_float4(0.f, 0.f, 0.f, 0.f);
        int e = beg;
        for (; e + 1 < end; e += 2) {
            int2 er0 = g_edge[e];
            int2 er1 = g_edge[e + 1];
            const float4* r0 = (const float4*)(xin + (size_t)er0.x * xstride);
            const float4* r1 = (const float4*)(xin + (size_t)er1.x * xstride);
            float4 x0 = r0[lane];
            float4 x1 = r1[lane];
            float a0 = __int_as_float(er0.y);
            float a1 = __int_as_float(er1.y);
            acc.x = fmaf(a0, x0.x, acc.x); acc.y = fmaf(a0, x0.y, acc.y);
            acc.z = fmaf(a0, x0.z, acc.z); acc.w = fmaf(a0, x0.w, acc.w);
            acc.x = fmaf(a1, x1.x, acc.x); acc.y = fmaf(a1, x1.y, acc.y);
            acc.z = fmaf(a1, x1.z, acc.z); acc.w = fmaf(a1, x1.w, acc.w);
        }
        if (e < end) {
            int2 er = g_edge[e];
            const float4* r = (const float4*)(xin + (size_t)er.x * xstride);
            float4 xv = r[lane];
            float a = __int_as_float(er.y);
            acc.x = fmaf(a, xv.x, acc.x); acc.y = fmaf(a, xv.y, acc.y);
            acc.z = fmaf(a, xv.z, acc.z); acc.w = fmaf(a, xv.w, acc.w);
        }
        *(float4*)(&g_hn[(size_t)gw * 128 + lane * 4]) = acc;
    } else {
        float2 acc = make_float2(0.f, 0.f);
        int e = beg;
        for (; e + 1 < end; e += 2) {
            int2 er0 = g_edge[e];
            int2 er1 = g_edge[e + 1];
            const float2* r0 = (const float2*)(xin + (size_t)er0.x * xstride);
            const float2* r1 = (const float2*)(xin + (size_t)er1.x * xstride);
            float2 x0 = r0[lane];
            float2 x1 = r1[lane];
            float a0 = __int_as_float(er0.y);
            float a1 = __int_as_float(er1.y);
            acc.x = fmaf(a0, x0.x, acc.x); acc.y = fmaf(a0, x0.y, acc.y);
            acc.x = fmaf(a1, x1.x, acc.x); acc.y = fmaf(a1, x1.y, acc.y);
        }
        if (e < end) {
            int2 er = g_edge[e];
            const float2* r = (const float2*)(xin + (size_t)er.x * xstride);
            float2 xv = r[lane];
            float a = __int_as_float(er.y);
            acc.x = fmaf(a, xv.x, acc.x); acc.y = fmaf(a, xv.y, acc.y);
        }
        *(float2*)(&g_hn[(size_t)gw * 64 + lane * 2]) = acc;
    }
}

// ---------------- fused bi-interaction ----------------
// out[v, outcol+j] = lrelu((x+h)@W1 + b1) + lrelu((x*h)@W2 + b2)
// Block: NT nodes. Thread tile: NPT=8 nodes x NJ=2 cols. Threads = (OUT/2)*(NT/8).
template <int IN, int OUT, int NT>
__global__ void __launch_bounds__((OUT / 2) * (NT / 8))
k_fuse(const float* __restrict__ xin, int xstride,
       const float* __restrict__ W1, const float* __restrict__ b1,
       const float* __restrict__ W2, const float* __restrict__ b2,
       float* __restrict__ out, int outcol) {
    constexpr int NPT = 8, NJ = 2;
    constexpr int NTH = (OUT / NJ) * (NT / NPT);
    __shared__ float s[NT][IN];
    __shared__ float p[NT][IN];

    int tid = threadIdx.x;
    int v0 = blockIdx.x * NT;

    for (int i = tid; i < NT * IN; i += NTH) {
        int n = i / IN, k = i % IN;
        int v = v0 + n;
        float xv = 0.f, hv = 0.f;
        if (v < NN) {
            xv = xin[(size_t)v * xstride + k];
            hv = g_hn[(size_t)v * IN + k];
        }
        s[n][k] = xv + hv;
        p[n][k] = xv * hv;
    }
    __syncthreads();

    int jg = tid % (OUT / NJ);
    int ng = tid / (OUT / NJ);
    int j = jg * NJ;
    int nb = ng * NPT;

    float a1[NPT][NJ], a2[NPT][NJ];
    #pragma unroll
    for (int n = 0; n < NPT; n++) {
        a1[n][0] = b1[j];     a1[n][1] = b1[j + 1];
        a2[n][0] = b2[j];     a2[n][1] = b2[j + 1];
    }

    for (int k = 0; k < IN; k += 4) {
        float2 w1v[4], w2v[4];
        #pragma unroll
        for (int kk = 0; kk < 4; kk++) {
            w1v[kk] = *(const float2*)&W1[(size_t)(k + kk) * OUT + j];
            w2v[kk] = *(const float2*)&W2[(size_t)(k + kk) * OUT + j];
        }
        #pragma unroll
        for (int n = 0; n < NPT; n++) {
            float4 s4 = *(const float4*)&s[nb + n][k];
            float4 p4 = *(const float4*)&p[nb + n][k];
            a1[n][0] = fmaf(s4.x, w1v[0].x, a1[n][0]); a1[n][1] = fmaf(s4.x, w1v[0].y, a1[n][1]);
            a2[n][0] = fmaf(p4.x, w2v[0].x, a2[n][0]); a2[n][1] = fmaf(p4.x, w2v[0].y, a2[n][1]);
            a1[n][0] = fmaf(s4.y, w1v[1].x, a1[n][0]); a1[n][1] = fmaf(s4.y, w1v[1].y, a1[n][1]);
            a2[n][0] = fmaf(p4.y, w2v[1].x, a2[n][0]); a2[n][1] = fmaf(p4.y, w2v[1].y, a2[n][1]);
            a1[n][0] = fmaf(s4.z, w1v[2].x, a1[n][0]); a1[n][1] = fmaf(s4.z, w1v[2].y, a1[n][1]);
            a2[n][0] = fmaf(p4.z, w2v[2].x, a2[n][0]); a2[n][1] = fmaf(p4.z, w2v[2].y, a2[n][1]);
            a1[n][0] = fmaf(s4.w, w1v[3].x, a1[n][0]); a1[n][1] = fmaf(s4.w, w1v[3].y, a1[n][1]);
            a2[n][0] = fmaf(p4.w, w2v[3].x, a2[n][0]); a2[n][1] = fmaf(p4.w, w2v[3].y, a2[n][1]);
        }
    }

    #pragma unroll
    for (int n = 0; n < NPT; n++) {
        int v = v0 + nb + n;
        if (v < NN) {
            #pragma unroll
            for (int jj = 0; jj < NJ; jj++) {
                float r1 = a1[n][jj]; r1 = r1 > 0.f ? r1 : 0.01f * r1;
                float r2 = a2[n][jj]; r2 = r2 > 0.f ? r2 : 0.01f * r2;
                out[(size_t)v * 352 + outcol + j + jj] = r1 + r2;
            }
        }
    }
}

// ---------------- launch ----------------
extern "C" void kernel_launch(void* const* d_in, const int* in_sizes, int n_in,
                              void* d_out, int out_size) {
    const float* x    = (const float*)d_in[0];
    const int*   src  = (const int*)d_in[1];
    const int*   dst  = (const int*)d_in[2];
    const float* attn = (const float*)d_in[3];
    const float* W1_0 = (const float*)d_in[4];
    const float* b1_0 = (const float*)d_in[5];
    const float* W2_0 = (const float*)d_in[6];
    const float* b2_0 = (const float*)d_in[7];
    const float* W1_1 = (const float*)d_in[8];
    const float* b1_1 = (const float*)d_in[9];
    const float* W2_1 = (const float*)d_in[10];
    const float* b2_1 = (const float*)d_in[11];
    const float* W1_2 = (const float*)d_in[12];
    const float* b1_2 = (const float*)d_in[13];
    const float* W2_2 = (const float*)d_in[14];
    const float* b2_2 = (const float*)d_in[15];
    float* out = (float*)d_out;

    // CSR build
    k_zero_deg<<<(NN + 255) / 256, 256>>>();
    k_hist<<<(NE + 255) / 256, 256>>>(dst);
    k_scan<<<1, 1024>>>();
    k_scatter<<<(NE + 255) / 256, 256>>>(src, dst, attn);

    // output cols [0,128) = x
    k_copy_x<<<(NN * 32 + 255) / 256, 256>>>(x, out);

    const int aggBlocks = (NN * 32 + 255) / 256;

    // layer 0: IN=128 -> OUT=128, writes cols [128,256)
    k_agg<4><<<aggBlocks, 256>>>(x, 128);
    k_fuse<128, 128, 32><<<(NN + 31) / 32, 256>>>(x, 128, W1_0, b1_0, W2_0, b2_0, out, 128);

    // layer 1: IN=128 -> OUT=64, reads cols [128,256), writes [256,320)
    k_agg<4><<<aggBlocks, 256>>>(out + 128, 352);
    k_fuse<128, 64, 32><<<(NN + 31) / 32, 128>>>(out + 128, 352, W1_1, b1_1, W2_1, b2_1, out, 256);

    // layer 2: IN=64 -> OUT=32, reads cols [256,320), writes [320,352)
    k_agg<2><<<aggBlocks, 256>>>(out + 256, 352);
    k_fuse<64, 32, 64><<<(NN + 63) / 64, 128>>>(out + 256, 352, W1_2, b1_2, W2_2, b2_2, out, 320);
}

// round 2
// speedup vs baseline: 1.0133x; 1.0133x over previous
#include <cuda_runtime.h>
#include <cuda_fp16.h>
#include <cstdint>

#define NN 100000
#define NE 3200000

// ---------------- static device scratch (no allocations allowed) ----------------
__device__ int     g_deg[NN];
__device__ int     g_off[NN + 1];
__device__ int     g_cursor[NN];
__device__ int2    g_edge[NE];            // (src, bitcast(attn)) sorted by dst
__device__ float   g_hn[(size_t)NN * 128]; // aggregation result (fp32), stride = IN
__device__ __half2 g_xh[(size_t)NN * 64];  // fp16 mirror of x (128 cols)
__device__ __half2 g_hh[(size_t)NN * 64];  // fp16 mirror of current layer output

// ---------------- CSR build ----------------
__global__ void k_zero_deg() {
    int i = blockIdx.x * blockDim.x + threadIdx.x;
    if (i < NN) g_deg[i] = 0;
}

__global__ void k_hist(const int* __restrict__ dst) {
    int e = blockIdx.x * blockDim.x + threadIdx.x;
    if (e < NE) atomicAdd(&g_deg[dst[e]], 1);
}

// single-block scan: each thread serially owns a contiguous chunk
__global__ void k_scan() {
    __shared__ int part[1024];
    int tid = threadIdx.x;
    const int CH = (NN + 1023) / 1024;
    int beg = tid * CH;
    int end = beg + CH < NN ? beg + CH : NN;
    int s = 0;
    for (int i = beg; i < end; i++) s += g_deg[i];
    part[tid] = s;
    __syncthreads();
    #pragma unroll
    for (int off = 1; off < 1024; off <<= 1) {
        int t = (tid >= off) ? part[tid - off] : 0;
        __syncthreads();
        part[tid] += t;
        __syncthreads();
    }
    int run = tid ? part[tid - 1] : 0;
    for (int i = beg; i < end; i++) {
        int d = g_deg[i];
        g_off[i] = run;
        g_cursor[i] = run;
        run += d;
    }
    if (tid == 1023) g_off[NN] = run;
}

__global__ void k_scatter(const int* __restrict__ src, const int* __restrict__ dst,
                          const float* __restrict__ attn) {
    int e = blockIdx.x * blockDim.x + threadIdx.x;
    if (e < NE) {
        int d = dst[e];
        int p = atomicAdd(&g_cursor[d], 1);
        g_edge[p] = make_int2(src[e], __float_as_int(attn[e]));
    }
}

// ---------------- copy x into output cols [0,128) + fp16 mirror ----------------
__global__ void k_copy_x(const float* __restrict__ x, float* __restrict__ out) {
    int t = blockIdx.x * blockDim.x + threadIdx.x;
    if (t < NN * 32) {
        int v = t >> 5, c = t & 31;
        float4 val = ((const float4*)(x + (size_t)v * 128))[c];
        ((float4*)(out + (size_t)v * 352))[c] = val;
        __half2 h0 = __floats2half2_rn(val.x, val.y);
        __half2 h1 = __floats2half2_rn(val.z, val.w);
        g_xh[(size_t)v * 64 + c * 2]     = h0;
        g_xh[(size_t)v * 64 + c * 2 + 1] = h1;
    }
}

// ---------------- aggregation: warp per dst node, CSR gather of fp16 rows ----------------
// VEC=4 -> D=128 (lane reads 4 halfs), VEC=2 -> D=64 (lane reads 2 halfs)
template <int VEC>
__global__ void k_agg(const __half2* __restrict__ xin) {
    int gw = (blockIdx.x * blockDim.x + threadIdx.x) >> 5;
    if (gw >= NN) return;
    int lane = threadIdx.x & 31;
    int beg = g_off[gw], end = g_off[gw + 1];

    if (VEC == 4) {
        float4 acc = make_float4(0.f, 0.f, 0.f, 0.f);
        int e = beg;
        for (; e + 1 < end; e += 2) {
            int2 er0 = g_edge[e];
            int2 er1 = g_edge[e + 1];
            float2 raw0 = ((const float2*)(xin + (size_t)er0.x * 64))[lane];
            float2 raw1 = ((const float2*)(xin + (size_t)er1.x * 64))[lane];
            float a0 = __int_as_float(er0.y);
            float a1 = __int_as_float(er1.y);
            float2 p0 = __half22float2(*(const __half2*)&raw0.x);
            float2 p1 = __half22float2(*(const __half2*)&raw0.y);
            acc.x = fmaf(a0, p0.x, acc.x); acc.y = fmaf(a0, p0.y, acc.y);
            acc.z = fmaf(a0, p1.x, acc.z); acc.w = fmaf(a0, p1.y, acc.w);
            float2 q0 = __half22float2(*(const __half2*)&raw1.x);
            float2 q1 = __half22float2(*(const __half2*)&raw1.y);
            acc.x = fmaf(a1, q0.x, acc.x); acc.y = fmaf(a1, q0.y, acc.y);
            acc.z = fmaf(a1, q1.x, acc.z); acc.w = fmaf(a1, q1.y, acc.w);
        }
        if (e < end) {
            int2 er = g_edge[e];
            float2 raw = ((const float2*)(xin + (size_t)er.x * 64))[lane];
            float a = __int_as_float(er.y);
            float2 p0 = __half22float2(*(const __half2*)&raw.x);
            float2 p1 = __half22float2(*(const __half2*)&raw.y);
            acc.x = fmaf(a, p0.x, acc.x); acc.y = fmaf(a, p0.y, acc.y);
            acc.z = fmaf(a, p1.x, acc.z); acc.w = fmaf(a, p1.y, acc.w);
        }
        *(float4*)(&g_hn[(size_t)gw * 128 + lane * 4]) = acc;
    } else {
        float2 acc = make_float2(0.f, 0.f);
        int e = beg;
        for (; e + 1 < end; e += 2) {
            int2 er0 = g_edge[e];
            int2 er1 = g_edge[e + 1];
            __half2 h0 = xin[(size_t)er0.x * 32 + lane];
            __half2 h1 = xin[(size_t)er1.x * 32 + lane];
            float a0 = __int_as_float(er0.y);
            float a1 = __int_as_float(er1.y);
            float2 p0 = __half22float2(h0);
            float2 p1 = __half22float2(h1);
            acc.x = fmaf(a0, p0.x, acc.x); acc.y = fmaf(a0, p0.y, acc.y);
            acc.x = fmaf(a1, p1.x, acc.x); acc.y = fmaf(a1, p1.y, acc.y);
        }
        if (e < end) {
            int2 er = g_edge[e];
            __half2 h = xin[(size_t)er.x * 32 + lane];
            float a = __int_as_float(er.y);
            float2 p = __half22float2(h);
            acc.x = fmaf(a, p.x, acc.x); acc.y = fmaf(a, p.y, acc.y);
        }
        *(float2*)(&g_hn[(size_t)gw * 64 + lane * 2]) = acc;
    }
}

// ---------------- fused bi-interaction ----------------
// out[v, outcol+j] = lrelu((x+h)@W1 + b1) + lrelu((x*h)@W2 + b2)
// Block: NT nodes. Thread tile: NPT=8 nodes x NJ=2 cols. Optional fp16 mirror write.
template <int IN, int OUT, int NT>
__global__ void __launch_bounds__((OUT / 2) * (NT / 8))
k_fuse(const float* __restrict__ xin, int xstride,
       const float* __restrict__ W1, const float* __restrict__ b1,
       const float* __restrict__ W2, const float* __restrict__ b2,
       float* __restrict__ out, int outcol, __half2* __restrict__ hh) {
    constexpr int NPT = 8, NJ = 2;
    constexpr int NTH = (OUT / NJ) * (NT / NPT);
    __shared__ float s[NT][IN];
    __shared__ float p[NT][IN];

    int tid = threadIdx.x;
    int v0 = blockIdx.x * NT;

    for (int i = tid; i < NT * IN; i += NTH) {
        int n = i / IN, k = i % IN;
        int v = v0 + n;
        float xv = 0.f, hv = 0.f;
        if (v < NN) {
            xv = xin[(size_t)v * xstride + k];
            hv = g_hn[(size_t)v * IN + k];
        }
        s[n][k] = xv + hv;
        p[n][k] = xv * hv;
    }
    __syncthreads();

    int jg = tid % (OUT / NJ);
    int ng = tid / (OUT / NJ);
    int j = jg * NJ;
    int nb = ng * NPT;

    float a1[NPT][NJ], a2[NPT][NJ];
    #pragma unroll
    for (int n = 0; n < NPT; n++) {
        a1[n][0] = b1[j];     a1[n][1] = b1[j + 1];
        a2[n][0] = b2[j];     a2[n][1] = b2[j + 1];
    }

    for (int k = 0; k < IN; k += 4) {
        float2 w1v[4], w2v[4];
        #pragma unroll
        for (int kk = 0; kk < 4; kk++) {
            w1v[kk] = *(const float2*)&W1[(size_t)(k + kk) * OUT + j];
            w2v[kk] = *(const float2*)&W2[(size_t)(k + kk) * OUT + j];
        }
        #pragma unroll
        for (int n = 0; n < NPT; n++) {
            float4 s4 = *(const float4*)&s[nb + n][k];
            float4 p4 = *(const float4*)&p[nb + n][k];
            a1[n][0] = fmaf(s4.x, w1v[0].x, a1[n][0]); a1[n][1] = fmaf(s4.x, w1v[0].y, a1[n][1]);
            a2[n][0] = fmaf(p4.x, w2v[0].x, a2[n][0]); a2[n][1] = fmaf(p4.x, w2v[0].y, a2[n][1]);
            a1[n][0] = fmaf(s4.y, w1v[1].x, a1[n][0]); a1[n][1] = fmaf(s4.y, w1v[1].y, a1[n][1]);
            a2[n][0] = fmaf(p4.y, w2v[1].x, a2[n][0]); a2[n][1] = fmaf(p4.y, w2v[1].y, a2[n][1]);
            a1[n][0] = fmaf(s4.z, w1v[2].x, a1[n][0]); a1[n][1] = fmaf(s4.z, w1v[2].y, a1[n][1]);
            a2[n][0] = fmaf(p4.z, w2v[2].x, a2[n][0]); a2[n][1] = fmaf(p4.z, w2v[2].y, a2[n][1]);
            a1[n][0] = fmaf(s4.w, w1v[3].x, a1[n][0]); a1[n][1] = fmaf(s4.w, w1v[3].y, a1[n][1]);
            a2[n][0] = fmaf(p4.w, w2v[3].x, a2[n][0]); a2[n][1] = fmaf(p4.w, w2v[3].y, a2[n][1]);
        }
    }

    #pragma unroll
    for (int n = 0; n < NPT; n++) {
        int v = v0 + nb + n;
        if (v < NN) {
            float r[NJ];
            #pragma unroll
            for (int jj = 0; jj < NJ; jj++) {
                float r1 = a1[n][jj]; r1 = r1 > 0.f ? r1 : 0.01f * r1;
                float r2 = a2[n][jj]; r2 = r2 > 0.f ? r2 : 0.01f * r2;
                r[jj] = r1 + r2;
                out[(size_t)v * 352 + outcol + j + jj] = r[jj];
            }
            if (hh) hh[(size_t)v * (OUT / 2) + (j >> 1)] = __floats2half2_rn(r[0], r[1]);
        }
    }
}

// ---------------- launch ----------------
extern "C" void kernel_launch(void* const* d_in, const int* in_sizes, int n_in,
                              void* d_out, int out_size) {
    const float* x    = (const float*)d_in[0];
    const int*   src  = (const int*)d_in[1];
    const int*   dst  = (const int*)d_in[2];
    const float* attn = (const float*)d_in[3];
    const float* W1_0 = (const float*)d_in[4];
    const float* b1_0 = (const float*)d_in[5];
    const float* W2_0 = (const float*)d_in[6];
    const float* b2_0 = (const float*)d_in[7];
    const float* W1_1 = (const float*)d_in[8];
    const float* b1_1 = (const float*)d_in[9];
    const float* W2_1 = (const float*)d_in[10];
    const float* b2_1 = (const float*)d_in[11];
    const float* W1_2 = (const float*)d_in[12];
    const float* b1_2 = (const float*)d_in[13];
    const float* W2_2 = (const float*)d_in[14];
    const float* b2_2 = (const float*)d_in[15];
    float* out = (float*)d_out;

    __half2* xh;
    __half2* hh;
    cudaGetSymbolAddress((void**)&xh, g_xh);
    cudaGetSymbolAddress((void**)&hh, g_hh);

    // CSR build
    k_zero_deg<<<(NN + 255) / 256, 256>>>();
    k_hist<<<(NE + 255) / 256, 256>>>(dst);
    k_scan<<<1, 1024>>>();
    k_scatter<<<(NE + 255) / 256, 256>>>(src, dst, attn);

    // output cols [0,128) = x ; also build fp16 mirror of x
    k_copy_x<<<(NN * 32 + 255) / 256, 256>>>(x, out);

    const int aggBlocks = (NN * 32 + 255) / 256;

    // layer 0: IN=128 -> OUT=128, writes cols [128,256) + fp16 mirror
    k_agg<4><<<aggBlocks, 256>>>(xh);
    k_fuse<128, 128, 32><<<(NN + 31) / 32, 256>>>(x, 128, W1_0, b1_0, W2_0, b2_0, out, 128, hh);

    // layer 1: IN=128 -> OUT=64, reads mirror h1, writes [256,320) + fp16 mirror
    k_agg<4><<<aggBlocks, 256>>>(hh);
    k_fuse<128, 64, 32><<<(NN + 31) / 32, 128>>>(out + 128, 352, W1_1, b1_1, W2_1, b2_1, out, 256, hh);

    // layer 2: IN=64 -> OUT=32, reads mirror h2, writes [320,352)
    k_agg<2><<<aggBlocks, 256>>>(hh);
    k_fuse<64, 32, 64><<<(NN + 63) / 64, 128>>>(out + 256, 352, W1_2, b1_2, W2_2, b2_2, out, 320, nullptr);
}

// round 3
// speedup vs baseline: 1.2636x; 1.2470x over previous
#include <cuda_runtime.h>
#include <cuda_fp16.h>
#include <mma.h>
#include <cstdint>

using namespace nvcuda;

#define NN 100000
#define NE 3200000

// ---------------- static device scratch (no allocations allowed) ----------------
__device__ int     g_deg[NN];
__device__ int     g_off[NN + 1];
__device__ int     g_cursor[NN];
__device__ int2    g_edge[NE];             // (src, bitcast(attn)) sorted by dst
__device__ float   g_hn[(size_t)NN * 128]; // aggregation result (fp32), stride = IN
__device__ __half2 g_xh[(size_t)NN * 64];  // fp16 mirror of x (128 cols)
__device__ __half2 g_hh[(size_t)NN * 64];  // fp16 mirror of current layer output
// fp16 weights
__device__ half g_w1_0[128 * 128];
__device__ half g_w2_0[128 * 128];
__device__ half g_w1_1[128 * 64];
__device__ half g_w2_1[128 * 64];
__device__ half g_w1_2[64 * 32];
__device__ half g_w2_2[64 * 32];

// ---------------- CSR build ----------------
__global__ void k_zero_deg() {
    int i = blockIdx.x * blockDim.x + threadIdx.x;
    if (i < NN) g_deg[i] = 0;
}

__global__ void k_hist(const int* __restrict__ dst) {
    int e = blockIdx.x * blockDim.x + threadIdx.x;
    if (e < NE) atomicAdd(&g_deg[dst[e]], 1);
}

// single-block scan: each thread serially owns a contiguous chunk
__global__ void k_scan() {
    __shared__ int part[1024];
    int tid = threadIdx.x;
    const int CH = (NN + 1023) / 1024;
    int beg = tid * CH;
    int end = beg + CH < NN ? beg + CH : NN;
    int s = 0;
    for (int i = beg; i < end; i++) s += g_deg[i];
    part[tid] = s;
    __syncthreads();
    #pragma unroll
    for (int off = 1; off < 1024; off <<= 1) {
        int t = (tid >= off) ? part[tid - off] : 0;
        __syncthreads();
        part[tid] += t;
        __syncthreads();
    }
    int run = tid ? part[tid - 1] : 0;
    for (int i = beg; i < end; i++) {
        int d = g_deg[i];
        g_off[i] = run;
        g_cursor[i] = run;
        run += d;
    }
    if (tid == 1023) g_off[NN] = run;
}

__global__ void k_scatter(const int* __restrict__ src, const int* __restrict__ dst,
                          const float* __restrict__ attn) {
    int e = blockIdx.x * blockDim.x + threadIdx.x;
    if (e < NE) {
        int d = dst[e];
        int p = atomicAdd(&g_cursor[d], 1);
        g_edge[p] = make_int2(src[e], __float_as_int(attn[e]));
    }
}

// ---------------- weight fp32 -> fp16 ----------------
__global__ void k_convw(const float* __restrict__ W, half* __restrict__ Wh, int n) {
    int i = blockIdx.x * blockDim.x + threadIdx.x;
    if (i < n) Wh[i] = __float2half(W[i]);
}

// ---------------- copy x into output cols [0,128) + fp16 mirror ----------------
__global__ void k_copy_x(const float* __restrict__ x, float* __restrict__ out) {
    int t = blockIdx.x * blockDim.x + threadIdx.x;
    if (t < NN * 32) {
        int v = t >> 5, c = t & 31;
        float4 val = ((const float4*)(x + (size_t)v * 128))[c];
        ((float4*)(out + (size_t)v * 352))[c] = val;
        g_xh[(size_t)v * 64 + c * 2]     = __floats2half2_rn(val.x, val.y);
        g_xh[(size_t)v * 64 + c * 2 + 1] = __floats2half2_rn(val.z, val.w);
    }
}

// ---------------- aggregation: warp per dst node, CSR gather of fp16 rows ----------------
template <int VEC>
__global__ void k_agg(const __half2* __restrict__ xin) {
    int gw = (blockIdx.x * blockDim.x + threadIdx.x) >> 5;
    if (gw >= NN) return;
    int lane = threadIdx.x & 31;
    int beg = g_off[gw], end = g_off[gw + 1];

    if (VEC == 4) {
        float4 acc = make_float4(0.f, 0.f, 0.f, 0.f);
        int e = beg;
        for (; e + 3 < end; e += 4) {
            int2 er0 = g_edge[e];
            int2 er1 = g_edge[e + 1];
            int2 er2 = g_edge[e + 2];
            int2 er3 = g_edge[e + 3];
            float2 raw0 = ((const float2*)(xin + (size_t)er0.x * 64))[lane];
            float2 raw1 = ((const float2*)(xin + (size_t)er1.x * 64))[lane];
            float2 raw2 = ((const float2*)(xin + (size_t)er2.x * 64))[lane];
            float2 raw3 = ((const float2*)(xin + (size_t)er3.x * 64))[lane];
            float a0 = __int_as_float(er0.y), a1 = __int_as_float(er1.y);
            float a2 = __int_as_float(er2.y), a3 = __int_as_float(er3.y);
            float2 p;
            p = __half22float2(*(const __half2*)&raw0.x);
            acc.x = fmaf(a0, p.x, acc.x); acc.y = fmaf(a0, p.y, acc.y);
            p = __half22float2(*(const __half2*)&raw0.y);
            acc.z = fmaf(a0, p.x, acc.z); acc.w = fmaf(a0, p.y, acc.w);
            p = __half22float2(*(const __half2*)&raw1.x);
            acc.x = fmaf(a1, p.x, acc.x); acc.y = fmaf(a1, p.y, acc.y);
            p = __half22float2(*(const __half2*)&raw1.y);
            acc.z = fmaf(a1, p.x, acc.z); acc.w = fmaf(a1, p.y, acc.w);
            p = __half22float2(*(const __half2*)&raw2.x);
            acc.x = fmaf(a2, p.x, acc.x); acc.y = fmaf(a2, p.y, acc.y);
            p = __half22float2(*(const __half2*)&raw2.y);
            acc.z = fmaf(a2, p.x, acc.z); acc.w = fmaf(a2, p.y, acc.w);
            p = __half22float2(*(const __half2*)&raw3.x);
            acc.x = fmaf(a3, p.x, acc.x); acc.y = fmaf(a3, p.y, acc.y);
            p = __half22float2(*(const __half2*)&raw3.y);
            acc.z = fmaf(a3, p.x, acc.z); acc.w = fmaf(a3, p.y, acc.w);
        }
        for (; e < end; e++) {
            int2 er = g_edge[e];
            float2 raw = ((const float2*)(xin + (size_t)er.x * 64))[lane];
            float a = __int_as_float(er.y);
            float2 p0 = __half22float2(*(const __half2*)&raw.x);
            float2 p1 = __half22float2(*(const __half2*)&raw.y);
            acc.x = fmaf(a, p0.x, acc.x); acc.y = fmaf(a, p0.y, acc.y);
            acc.z = fmaf(a, p1.x, acc.z); acc.w = fmaf(a, p1.y, acc.w);
        }
        *(float4*)(&g_hn[(size_t)gw * 128 + lane * 4]) = acc;
    } else {
        float2 acc = make_float2(0.f, 0.f);
        int e = beg;
        for (; e + 3 < end; e += 4) {
            int2 er0 = g_edge[e];
            int2 er1 = g_edge[e + 1];
            int2 er2 = g_edge[e + 2];
            int2 er3 = g_edge[e + 3];
            __half2 h0 = xin[(size_t)er0.x * 32 + lane];
            __half2 h1 = xin[(size_t)er1.x * 32 + lane];
            __half2 h2 = xin[(size_t)er2.x * 32 + lane];
            __half2 h3 = xin[(size_t)er3.x * 32 + lane];
            float2 p;
            p = __half22float2(h0); float a0 = __int_as_float(er0.y);
            acc.x = fmaf(a0, p.x, acc.x); acc.y = fmaf(a0, p.y, acc.y);
            p = __half22float2(h1); float a1 = __int_as_float(er1.y);
            acc.x = fmaf(a1, p.x, acc.x); acc.y = fmaf(a1, p.y, acc.y);
            p = __half22float2(h2); float a2 = __int_as_float(er2.y);
            acc.x = fmaf(a2, p.x, acc.x); acc.y = fmaf(a2, p.y, acc.y);
            p = __half22float2(h3); float a3 = __int_as_float(er3.y);
            acc.x = fmaf(a3, p.x, acc.x); acc.y = fmaf(a3, p.y, acc.y);
        }
        for (; e < end; e++) {
            int2 er = g_edge[e];
            __half2 h = xin[(size_t)er.x * 32 + lane];
            float a = __int_as_float(er.y);
            float2 p = __half22float2(h);
            acc.x = fmaf(a, p.x, acc.x); acc.y = fmaf(a, p.y, acc.y);
        }
        *(float2*)(&g_hn[(size_t)gw * 64 + lane * 2]) = acc;
    }
}

// ---------------- fused bi-interaction via wmma (HMMA) ----------------
// out[v, outcol+j] = lrelu((x+h)@W1 + b1) + lrelu((x*h)@W2 + b2)
// 128 threads = 4 warps; block tile BM=64 nodes x BN cols; warp tile 32 x BN/2.
template <int IN, int OUT, int BN>
__global__ void __launch_bounds__(128)
k_fuse_mma(const float* __restrict__ xin, int xstride,
           const half* __restrict__ W1h, const float* __restrict__ b1,
           const half* __restrict__ W2h, const float* __restrict__ b2,
           float* __restrict__ out, int outcol, __half2* __restrict__ hh) {
    constexpr int BM = 64;
    constexpr int NF = BN / 32;                // 16-wide n-frags per warp
    constexpr size_t OPER_BYTES = (size_t)2 * BM * IN * sizeof(half);
    constexpr size_t EPI_BYTES  = (size_t)2 * BM * BN * sizeof(float);
    constexpr size_t SBYTES = OPER_BYTES > EPI_BYTES ? OPER_BYTES : EPI_BYTES;
    __shared__ __align__(16) char sm[SBYTES];
    half*  s_s = (half*)sm;                    // [BM][IN]
    half*  s_p = s_s + (size_t)BM * IN;        // [BM][IN]
    float* o1  = (float*)sm;                   // [BM][BN] (aliases s_s/s_p after sync)
    float* o2  = o1 + (size_t)BM * BN;

    int tid = threadIdx.x;
    int wid = tid >> 5;
    int v0 = blockIdx.x * BM;
    int j0 = blockIdx.y * BN;

    // build S = x+h, P = x*h (fp16)
    for (int i = tid; i < BM * (IN / 2); i += 128) {
        int n = i / (IN / 2), k2 = i % (IN / 2);
        int v = v0 + n;
        float2 xv = make_float2(0.f, 0.f), hv = make_float2(0.f, 0.f);
        if (v < NN) {
            xv = *(const float2*)&xin[(size_t)v * xstride + k2 * 2];
            hv = *(const float2*)&g_hn[(size_t)v * IN + k2 * 2];
        }
        *(__half2*)&s_s[(size_t)n * IN + k2 * 2] = __floats2half2_rn(xv.x + hv.x, xv.y + hv.y);
        *(__half2*)&s_p[(size_t)n * IN + k2 * 2] = __floats2half2_rn(xv.x * hv.x, xv.y * hv.y);
    }
    __syncthreads();

    int wm = wid >> 1;  // 0..1 : row group
    int wn = wid & 1;   // 0..1 : col group

    wmma::fragment<wmma::accumulator, 16, 16, 16, float> acc1[2][NF], acc2[2][NF];
    #pragma unroll
    for (int mi = 0; mi < 2; mi++)
        #pragma unroll
        for (int ni = 0; ni < NF; ni++) {
            wmma::fill_fragment(acc1[mi][ni], 0.f);
            wmma::fill_fragment(acc2[mi][ni], 0.f);
        }

    for (int kc = 0; kc < IN; kc += 16) {
        wmma::fragment<wmma::matrix_a, 16, 16, 16, half, wmma::row_major> a1[2], a2[2];
        #pragma unroll
        for (int mi = 0; mi < 2; mi++) {
            wmma::load_matrix_sync(a1[mi], &s_s[(size_t)(wm * 32 + mi * 16) * IN + kc], IN);
            wmma::load_matrix_sync(a2[mi], &s_p[(size_t)(wm * 32 + mi * 16) * IN + kc], IN);
        }
        #pragma unroll
        for (int ni = 0; ni < NF; ni++) {
            int j = j0 + wn * (BN / 2) + ni * 16;
            wmma::fragment<wmma::matrix_b, 16, 16, 16, half, wmma::row_major> bf1, bf2;
            wmma::load_matrix_sync(bf1, &W1h[(size_t)kc * OUT + j], OUT);
            wmma::load_matrix_sync(bf2, &W2h[(size_t)kc * OUT + j], OUT);
            #pragma unroll
            for (int mi = 0; mi < 2; mi++) {
                wmma::mma_sync(acc1[mi][ni], a1[mi], bf1, acc1[mi][ni]);
                wmma::mma_sync(acc2[mi][ni], a2[mi], bf2, acc2[mi][ni]);
            }
        }
    }

    __syncthreads();  // operand tiles dead; reuse as epilogue buffers
    #pragma unroll
    for (int mi = 0; mi < 2; mi++)
        #pragma unroll
        for (int ni = 0; ni < NF; ni++) {
            int r = wm * 32 + mi * 16;
            int c = wn * (BN / 2) + ni * 16;
            wmma::store_matrix_sync(&o1[(size_t)r * BN + c], acc1[mi][ni], BN, wmma::mem_row_major);
            wmma::store_matrix_sync(&o2[(size_t)r * BN + c], acc2[mi][ni], BN, wmma::mem_row_major);
        }
    __syncthreads();

    for (int i = tid; i < BM * (BN / 2); i += 128) {
        int n = i / (BN / 2), j2 = i % (BN / 2);
        int v = v0 + n;
        if (v < NN) {
            int j = j2 * 2;
            float r1a = o1[(size_t)n * BN + j]     + b1[j0 + j];
            float r1b = o1[(size_t)n * BN + j + 1] + b1[j0 + j + 1];
            float r2a = o2[(size_t)n * BN + j]     + b2[j0 + j];
            float r2b = o2[(size_t)n * BN + j + 1] + b2[j0 + j + 1];
            r1a = r1a > 0.f ? r1a : 0.01f * r1a;
            r1b = r1b > 0.f ? r1b : 0.01f * r1b;
            r2a = r2a > 0.f ? r2a : 0.01f * r2a;
            r2b = r2b > 0.f ? r2b : 0.01f * r2b;
            float ra = r1a + r2a, rb = r1b + r2b;
            *(float2*)&out[(size_t)v * 352 + outcol + j0 + j] = make_float2(ra, rb);
            if (hh) hh[(size_t)v * (OUT / 2) + ((j0 + j) >> 1)] = __floats2half2_rn(ra, rb);
        }
    }
}

// ---------------- launch ----------------
extern "C" void kernel_launch(void* const* d_in, const int* in_sizes, int n_in,
                              void* d_out, int out_size) {
    const float* x    = (const float*)d_in[0];
    const int*   src  = (const int*)d_in[1];
    const int*   dst  = (const int*)d_in[2];
    const float* attn = (const float*)d_in[3];
    const float* W1_0 = (const float*)d_in[4];
    const float* b1_0 = (const float*)d_in[5];
    const float* W2_0 = (const float*)d_in[6];
    const float* b2_0 = (const float*)d_in[7];
    const float* W1_1 = (const float*)d_in[8];
    const float* b1_1 = (const float*)d_in[9];
    const float* W2_1 = (const float*)d_in[10];
    const float* b2_1 = (const float*)d_in[11];
    const float* W1_2 = (const float*)d_in[12];
    const float* b1_2 = (const float*)d_in[13];
    const float* W2_2 = (const float*)d_in[14];
    const float* b2_2 = (const float*)d_in[15];
    float* out = (float*)d_out;

    __half2 *xh, *hh;
    half *w1_0, *w2_0, *w1_1, *w2_1, *w1_2, *w2_2;
    cudaGetSymbolAddress((void**)&xh, g_xh);
    cudaGetSymbolAddress((void**)&hh, g_hh);
    cudaGetSymbolAddress((void**)&w1_0, g_w1_0);
    cudaGetSymbolAddress((void**)&w2_0, g_w2_0);
    cudaGetSymbolAddress((void**)&w1_1, g_w1_1);
    cudaGetSymbolAddress((void**)&w2_1, g_w2_1);
    cudaGetSymbolAddress((void**)&w1_2, g_w1_2);
    cudaGetSymbolAddress((void**)&w2_2, g_w2_2);

    // CSR build
    k_zero_deg<<<(NN + 255) / 256, 256>>>();
    k_hist<<<(NE + 255) / 256, 256>>>(dst);
    k_scan<<<1, 1024>>>();
    k_scatter<<<(NE + 255) / 256, 256>>>(src, dst, attn);

    // fp16 weights
    k_convw<<<(128 * 128 + 255) / 256, 256>>>(W1_0, w1_0, 128 * 128);
    k_convw<<<(128 * 128 + 255) / 256, 256>>>(W2_0, w2_0, 128 * 128);
    k_convw<<<(128 * 64 + 255) / 256, 256>>>(W1_1, w1_1, 128 * 64);
    k_convw<<<(128 * 64 + 255) / 256, 256>>>(W2_1, w2_1, 128 * 64);
    k_convw<<<(64 * 32 + 255) / 256, 256>>>(W1_2, w1_2, 64 * 32);
    k_convw<<<(64 * 32 + 255) / 256, 256>>>(W2_2, w2_2, 64 * 32);

    // output cols [0,128) = x ; fp16 mirror of x
    k_copy_x<<<(NN * 32 + 255) / 256, 256>>>(x, out);

    const int aggBlocks = (NN * 32 + 255) / 256;
    const int fuseGrid = (NN + 63) / 64;

    // layer 0: IN=128 -> OUT=128
    k_agg<4><<<aggBlocks, 256>>>(xh);
    {
        dim3 g(fuseGrid, 2);
        k_fuse_mma<128, 128, 64><<<g, 128>>>(x, 128, w1_0, b1_0, w2_0, b2_0, out, 128, hh);
    }
    // layer 1: IN=128 -> OUT=64
    k_agg<4><<<aggBlocks, 256>>>(hh);
    {
        dim3 g(fuseGrid, 1);
        k_fuse_mma<128, 64, 64><<<g, 128>>>(out + 128, 352, w1_1, b1_1, w2_1, b2_1, out, 256, hh);
    }
    // layer 2: IN=64 -> OUT=32
    k_agg<2><<<aggBlocks, 256>>>(hh);
    {
        dim3 g(fuseGrid, 1);
        k_fuse_mma<64, 32, 32><<<g, 128>>>(out + 256, 352, w1_2, b1_2, w2_2, b2_2, out, 320, nullptr);
    }
}